// round 11
// baseline (speedup 1.0000x reference)
#include <cuda_runtime.h>
#include <cuda_bf16.h>
#include <cstdint>

// RotationComponent: w_rotated = w @ rot, a_rotated = x @ rot, rot a
// normalized randomized Hadamard: rot[i,j] = H[i,j] * rot[0,j], H Sylvester,
// rot[0,j] = s_j * 2^-6 exactly (s_j = +-1, 2^-6 exact in fp32). Hence
//   (v @ rot)[j] = FWHT(v)[j] * s_j * 2^-6.
//
// One CTA per row (round-6 structure: coalesced LDG input, natural regs).
// The epilogue sign pattern depends ONLY on threadIdx (every CTA's thread t
// owns the same columns i = c*1024 + t*4 + e), so a one-shot setup kernel
// precomputes a 256-entry uint16-style mask table; the hot kernel reads one
// word per thread and applies sign via XOR + exact 2^-6 multiply. This
// removes 16 rot-load L1 wavefronts/thread and all per-CTA packing ALU.
//
// FWHT phases (shuffle-free, conflict-free swizzled smem):
//   P1: regs = i-bits {9..6}   i = (t>>6)*1024 + r*64 + (t&63)  (LDG coalesced)
//   P2: regs = i-bits {5..2}   i = J*64 + r*4 + e2              (smem only)
//   P3: regs = i-bits {11,10,1,0} -> 4 aligned float4, STG.128
// Swizzle: phys = i ^ ((i>>4) & 28) (16B-granular, preserves LDS.128 blocks).

#define DIM 4096
#define W_ROWS 4096
#define THREADS 256
#define INV64 0.015625f

__device__ unsigned g_mask[THREADS];   // per-threadIdx sign masks (1 KB)

__global__ void pack_masks_kernel(const float* __restrict__ rot)
{
    const int t = threadIdx.x;          // 256 threads, one mask each
    unsigned m = 0;
    #pragma unroll
    for (int c = 0; c < 4; c++) {
        float4 s = __ldg((const float4*)(rot + c * 1024 + t * 4));
        m |= (__float_as_uint(s.x) >> 31) << (c * 4 + 0);
        m |= (__float_as_uint(s.y) >> 31) << (c * 4 + 1);
        m |= (__float_as_uint(s.z) >> 31) << (c * 4 + 2);
        m |= (__float_as_uint(s.w) >> 31) << (c * 4 + 3);
    }
    g_mask[t] = m;
}

__device__ __forceinline__ int swz(int i)
{
    return i ^ ((i >> 4) & 28);
}

__global__ __launch_bounds__(THREADS)
void fwht_rotate_kernel(const float* __restrict__ w,
                        const float* __restrict__ x,
                        float* __restrict__ out)
{
    __shared__ float buf[DIM];

    const int row  = blockIdx.x;
    const int t    = threadIdx.x;
    const int lane = t & 31;
    const int warp = t >> 5;

    const float* src = (row < W_ROWS)
        ? (w + (size_t)row * DIM)
        : (x + (size_t)(row - W_ROWS) * DIM);

    // ---- Per-thread sign mask: one coalesced LDG.32 ----
    const unsigned mask = g_mask[t];

    float v[16];

    // ---- P1: i = (t>>6)*1024 + r*64 + (t&63); LDG coalesced ----
    const int p1_base = (t >> 6) * 1024 + (t & 63);
    #pragma unroll
    for (int r = 0; r < 16; r++) {
        v[r] = src[p1_base + r * 64];
    }

    // ---- P1 butterflies: i-bits {9..6} ----
    #pragma unroll
    for (int m = 8; m >= 1; m >>= 1) {
        #pragma unroll
        for (int r = 0; r < 16; r++) {
            if ((r & m) == 0) {
                float a = v[r], b = v[r | m];
                v[r]     = a + b;
                v[r | m] = a - b;
            }
        }
    }

    // ---- T1: swizzled smem write (conflict-free) ----
    #pragma unroll
    for (int r = 0; r < 16; r++) {
        buf[swz(p1_base + r * 64)] = v[r];
    }
    __syncthreads();

    // ---- P2: i = J*64 + r*4 + e2; butterflies on i-bits {5..2} ----
    const int p2_base = (warp * 8 + ((lane >> 2) & 7)) * 64 + (lane & 3);
    #pragma unroll
    for (int r = 0; r < 16; r++) {
        v[r] = buf[swz(p2_base + r * 4)];
    }
    #pragma unroll
    for (int m = 8; m >= 1; m >>= 1) {
        #pragma unroll
        for (int r = 0; r < 16; r++) {
            if ((r & m) == 0) {
                float a = v[r], b = v[r | m];
                v[r]     = a + b;
                v[r | m] = a - b;
            }
        }
    }
    // ---- T2: write back to the same per-thread addresses ----
    #pragma unroll
    for (int r = 0; r < 16; r++) {
        buf[swz(p2_base + r * 4)] = v[r];
    }
    __syncthreads();

    // ---- P3: i = c*1024 + t*4 + e; LDS.128; butterflies {11,10,1,0} ----
    const int p3_base = t * 4;
    #pragma unroll
    for (int c = 0; c < 4; c++) {
        float4 q = *(const float4*)(buf + swz(c * 1024 + p3_base));
        v[c * 4 + 0] = q.x;
        v[c * 4 + 1] = q.y;
        v[c * 4 + 2] = q.z;
        v[c * 4 + 3] = q.w;
    }
    #pragma unroll
    for (int m = 8; m >= 1; m >>= 1) {
        #pragma unroll
        for (int r = 0; r < 16; r++) {
            if ((r & m) == 0) {
                float a = v[r], b = v[r | m];
                v[r]     = a + b;
                v[r | m] = a - b;
            }
        }
    }

    // ---- Epilogue: sign-XOR + exact 2^-6 scale, 4x STG.128 ----
    float* dst = out + (size_t)row * DIM;
    #pragma unroll
    for (int c = 0; c < 4; c++) {
        float4 o;
        #pragma unroll
        for (int e = 0; e < 4; e++) {
            const int k = c * 4 + e;
            const unsigned sb = (mask >> k) << 31;
            ((float*)&o)[e] =
                __int_as_float(__float_as_int(v[k]) ^ (int)sb) * INV64;
        }
        *(float4*)(dst + c * 1024 + p3_base) = o;
    }
}

extern "C" void kernel_launch(void* const* d_in, const int* in_sizes, int n_in,
                              void* d_out, int out_size)
{
    const float* w   = (const float*)d_in[0];   // [4096, 4096]
    const float* x   = (const float*)d_in[1];   // [4, 2048, 4096]
    const float* rot = (const float*)d_in[2];   // [4096, 4096]
    float* out = (float*)d_out;                 // w_rotated then a_rotated

    (void)in_sizes; (void)n_in; (void)out_size;

    pack_masks_kernel<<<1, THREADS>>>(rot);
    fwht_rotate_kernel<<<12288, THREADS>>>(w, x, out);
}